// round 7
// baseline (speedup 1.0000x reference)
#include <cuda_runtime.h>

// QuantumLayer via Pauli-transfer closed form.
//
// o_j = sum over 41 even-Y Pauli strings t in {I,X,Y}^4 of
//       W_j[t] * prod_w (1 | cos th_w | sin th_w),
// W computed once per launch by a tiny setup kernel (depends only on params).
//
// Main kernel: 4 batch items per thread, as TWO f32x2 lane-pairs (P = items
// 0,1; Q = items 2,3). Each weight LDS.64 is loaded once and feeds two packed
// FMAs, halving shared-memory traffic per item (LDS was the R5 binder).

typedef unsigned long long ull;

__device__ __forceinline__ ull pk(float a, float b) {
    ull r; asm("mov.b64 %0, {%1, %2};" : "=l"(r) : "f"(a), "f"(b)); return r;
}
__device__ __forceinline__ void upk(ull v, float& a, float& b) {
    asm("mov.b64 {%0, %1}, %2;" : "=f"(a), "=f"(b) : "l"(v));
}
__device__ __forceinline__ ull f2mul(ull a, ull b) {
    ull r; asm("mul.rn.f32x2 %0, %1, %2;" : "=l"(r) : "l"(a), "l"(b)); return r;
}
__device__ __forceinline__ ull f2fma(ull a, ull b, ull c) {
    ull r; asm("fma.rn.f32x2 %0, %1, %2, %3;" : "=l"(r) : "l"(a), "l"(b), "l"(c)); return r;
}

#define F2_ONE 0x3F8000003F800000ULL   // (1.0f, 1.0f)

// Weights: [j*41 + tIdx], j = output wire, tIdx = even-Y string index
// (lexicographic over t0*27+t1*9+t2*3+t3, wire0 = MSB).
__device__ float g_W[164];

// ---------------------------------------------------------------------------
// Setup kernel: grid = 164 blocks (one per (j, tIdx)), 32 threads each.
// ---------------------------------------------------------------------------

#define CNOTF(c_, t_)                                                         \
    {                                                                         \
        const int mc = 8 >> (c_), mt = 8 >> (t_);                             \
        _Pragma("unroll")                                                     \
        for (int k = 0; k < 16; ++k)                                          \
            if ((k & mc) && !(k & mt)) {                                      \
                float tmp = st[k]; st[k] = st[k | mt]; st[k | mt] = tmp;      \
            }                                                                 \
    }

__global__ void setup_weights(const float* __restrict__ params)
{
    __shared__ float sU[16][17];   // sU[m][k] = (U e_k)[m]
    const int tid = threadIdx.x;

    float pc[8], ps[8];
#pragma unroll
    for (int g = 0; g < 8; ++g) {
        float th = 0.5f * params[g];
        ps[g] = sinf(th); pc[g] = cosf(th);
    }

    if (tid < 16) {
        float st[16];
#pragma unroll
        for (int i = 0; i < 16; ++i) st[i] = 0.0f;
        st[tid] = 1.0f;
        CNOTF(0, 1); CNOTF(1, 2); CNOTF(2, 3);
#pragma unroll
        for (int layer = 0; layer < 2; ++layer) {
#pragma unroll
            for (int w = 0; w < 4; ++w) {
                const float c = pc[layer * 4 + w], s = ps[layer * 4 + w];
                const int m = 8 >> w;
#pragma unroll
                for (int k = 0; k < 16; ++k)
                    if (!(k & m)) {
                        const int k1 = k | m;
                        float a0 = st[k], a1 = st[k1];
                        st[k]  = c * a0 - s * a1;
                        st[k1] = s * a0 + c * a1;
                    }
            }
            CNOTF(0, 1); CNOTF(1, 2); CNOTF(2, 3); CNOTF(3, 0);
        }
#pragma unroll
        for (int m = 0; m < 16; ++m) sU[m][tid] = st[m];
    }
    __syncthreads();

    const int b = blockIdx.x;
    const int j = b / 41, tIdx = b % 41;
    int enc = 0, cnt = -1;
    for (int e = 0; e < 81; ++e) {
        int ny = ((e / 27) == 2) + (((e / 9) % 3) == 2) +
                 (((e / 3) % 3) == 2) + ((e % 3) == 2);
        if (!(ny & 1)) { if (++cnt == tIdx) { enc = e; break; } }
    }
    const int t0 = enc / 27, t1 = (enc / 9) % 3, t2 = (enc / 3) % 3, t3 = enc % 3;
    const int ny = (t0 == 2) + (t1 == 2) + (t2 == 2) + (t3 == 2);
    const int f  = (t0 ? 8 : 0) | (t1 ? 4 : 0) | (t2 ? 2 : 0) | (t3 ? 1 : 0);
    const float sign0 = (ny == 2) ? -1.0f : 1.0f;   // i^nY for even nY

    float part = 0.0f;
    if (tid < 16) {
        const int l = tid, lf = l ^ f;
        float vl = 1.0f;
        if (t0 == 2 && (l & 8)) vl = -vl;
        if (t1 == 2 && (l & 4)) vl = -vl;
        if (t2 == 2 && (l & 2)) vl = -vl;
        if (t3 == 2 && (l & 1)) vl = -vl;
        float oacc = 0.0f;                          // O_j[lf, l]
#pragma unroll
        for (int m = 0; m < 16; ++m) {
            float z = ((m >> (3 - j)) & 1) ? -1.0f : 1.0f;
            oacc += z * sU[m][lf] * sU[m][l];
        }
        part = vl * oacc;
    }
#pragma unroll
    for (int off = 16; off; off >>= 1)
        part += __shfl_down_sync(0xffffffff, part, off);
    if (tid == 0) g_W[b] = sign0 * part * (1.0f / 16.0f);
}

// ---------------------------------------------------------------------------
// Main kernel: 4 items per thread (two packed lane-pairs P and Q).
// ---------------------------------------------------------------------------

#define SINCOS2(dc, ds, xa, xb)                                               \
    { float sa_, ca_, sb_, cb_;                                               \
      __sincosf(xa, &sa_, &ca_); __sincosf(xb, &sb_, &cb_);                   \
      dc = pk(ca_, cb_); ds = pk(sa_, sb_); }

__global__ void __launch_bounds__(256)
quantum_layer_kernel(const float4* __restrict__ inp,
                     float4* __restrict__ out, int nquad, int B)
{
    __shared__ ull sW[164];   // weights duplicated into both lanes
    for (int i = threadIdx.x; i < 164; i += 256) {
        float w = g_W[i];
        sW[i] = pk(w, w);
    }
    __syncthreads();

    const int t = blockIdx.x * blockDim.x + threadIdx.x;
    if (t >= nquad) return;

    const int i0 = 4 * t;
    const bool hB = (i0 + 1) < B, hC = (i0 + 2) < B, hD = (i0 + 3) < B;
    float4 inA = inp[i0];
    float4 inB = hB ? inp[i0 + 1] : inA;
    float4 inC = hC ? inp[i0 + 2] : inA;
    float4 inD = hD ? inp[i0 + 3] : inA;

    // Full-angle cos/sin per wire, per lane-pair.
    ull CP[4], SP[4], CQ[4], SQ[4];
    SINCOS2(CP[0], SP[0], inA.x, inB.x); SINCOS2(CQ[0], SQ[0], inC.x, inD.x);
    SINCOS2(CP[1], SP[1], inA.y, inB.y); SINCOS2(CQ[1], SQ[1], inC.y, inD.y);
    SINCOS2(CP[2], SP[2], inA.z, inB.z); SINCOS2(CQ[2], SQ[2], inC.z, inD.z);
    SINCOS2(CP[3], SP[3], inA.w, inB.w); SINCOS2(CQ[3], SQ[3], inC.w, inD.w);

    // Monomials over wires 0,1 for each lane-pair.
    ull mP01[9], mQ01[9];
    mP01[0] = F2_ONE;               mQ01[0] = F2_ONE;
    mP01[1] = CP[1];                mQ01[1] = CQ[1];
    mP01[2] = SP[1];                mQ01[2] = SQ[1];
    mP01[3] = CP[0];                mQ01[3] = CQ[0];
    mP01[6] = SP[0];                mQ01[6] = SQ[0];
    mP01[4] = f2mul(CP[0], CP[1]);  mQ01[4] = f2mul(CQ[0], CQ[1]);
    mP01[5] = f2mul(CP[0], SP[1]);  mQ01[5] = f2mul(CQ[0], SQ[1]);
    mP01[7] = f2mul(SP[0], CP[1]);  mQ01[7] = f2mul(SQ[0], CQ[1]);
    mP01[8] = f2mul(SP[0], SP[1]);  mQ01[8] = f2mul(SQ[0], SQ[1]);

    ull oP0 = 0, oP1 = 0, oP2 = 0, oP3 = 0;
    ull oQ0 = 0, oQ1 = 0, oQ2 = 0, oQ3 = 0;
    int idx = 0;
#pragma unroll
    for (int t0 = 0; t0 < 3; ++t0)
#pragma unroll
    for (int t1 = 0; t1 < 3; ++t1) {
        const int p01 = t0 * 3 + t1;
#pragma unroll
        for (int t2 = 0; t2 < 3; ++t2) {
            ull preP, preQ;
            bool preOne = false;
            if (t2 == 0) {
                preP = mP01[p01]; preQ = mQ01[p01]; preOne = (p01 == 0);
            } else if (p01 == 0) {
                preP = (t2 == 1) ? CP[2] : SP[2];
                preQ = (t2 == 1) ? CQ[2] : SQ[2];
            } else {
                preP = f2mul(mP01[p01], (t2 == 1) ? CP[2] : SP[2]);
                preQ = f2mul(mQ01[p01], (t2 == 1) ? CQ[2] : SQ[2]);
            }
#pragma unroll
            for (int t3 = 0; t3 < 3; ++t3) {
                const int ny = (t0 == 2) + (t1 == 2) + (t2 == 2) + (t3 == 2);
                if (ny & 1) continue;   // odd-Y strings have zero weight
                ull mP, mQ;
                if (t3 == 0) {
                    mP = preP; mQ = preQ;
                } else if (preOne) {
                    mP = (t3 == 1) ? CP[3] : SP[3];
                    mQ = (t3 == 1) ? CQ[3] : SQ[3];
                } else {
                    mP = f2mul(preP, (t3 == 1) ? CP[3] : SP[3]);
                    mQ = f2mul(preQ, (t3 == 1) ? CQ[3] : SQ[3]);
                }
                // One LDS.64 per weight, reused by both lane-pairs.
                ull w0 = sW[idx], w1 = sW[41 + idx];
                ull w2 = sW[82 + idx], w3 = sW[123 + idx];
                oP0 = f2fma(mP, w0, oP0);  oQ0 = f2fma(mQ, w0, oQ0);
                oP1 = f2fma(mP, w1, oP1);  oQ1 = f2fma(mQ, w1, oQ1);
                oP2 = f2fma(mP, w2, oP2);  oQ2 = f2fma(mQ, w2, oQ2);
                oP3 = f2fma(mP, w3, oP3);  oQ3 = f2fma(mQ, w3, oQ3);
                ++idx;
            }
        }
    }

    float a0, b0, a1, b1, a2, b2, a3, b3;
    upk(oP0, a0, b0); upk(oP1, a1, b1); upk(oP2, a2, b2); upk(oP3, a3, b3);
    out[i0] = make_float4(a0, a1, a2, a3);
    if (hB) out[i0 + 1] = make_float4(b0, b1, b2, b3);
    upk(oQ0, a0, b0); upk(oQ1, a1, b1); upk(oQ2, a2, b2); upk(oQ3, a3, b3);
    if (hC) out[i0 + 2] = make_float4(a0, a1, a2, a3);
    if (hD) out[i0 + 3] = make_float4(b0, b1, b2, b3);
}

extern "C" void kernel_launch(void* const* d_in, const int* in_sizes, int n_in,
                              void* d_out, int out_size)
{
    const float* inputs = (const float*)d_in[0];   // (B, 4) float32
    const float* params = (const float*)d_in[1];   // (2, 4) float32
    float* outp = (float*)d_out;                   // (B, 4) float32

    int B = in_sizes[0] / 4;
    int nquad = (B + 3) / 4;
    int threads = 256;
    int blocks = (nquad + threads - 1) / threads;

    setup_weights<<<164, 32>>>(params);
    quantum_layer_kernel<<<blocks, threads>>>((const float4*)inputs,
                                              (float4*)outp, nquad, B);
}